// round 3
// baseline (speedup 1.0000x reference)
#include <cuda_runtime.h>

#define BATCH 32
#define HW    3136
#define C     256
#define C4    64          // C/4
#define CR    64
#define CPIX  32          // pixels per chunk
#define NCHUNK 98         // HW / CPIX

// Scratch (allocation-free per harness rules)
__device__ float g_partial[BATCH * NCHUNK * C];
__device__ float g_gate[BATCH * C];
__device__ int   g_count[BATCH];
__device__ volatile int g_flag[BATCH];

__global__ void init_kernel() {
    int t = threadIdx.x;
    if (t < BATCH) { g_count[t] = 0; g_flag[t] = 0; }
}

// ---------------------------------------------------------------------------
// Single fused kernel. grid = (NCHUNK, BATCH), block = 256 threads.
// Phase 1: load 32px x 256ch chunk (32KB) into SMEM with __ldcs, partial GAP.
// Sync:    per-batch counter; last block computes FC + gate, sets flag;
//          others spin (thread 0 + nanosleep).
// Phase 2: multiply SMEM-cached x by gate, streaming-store to out.
// x is read from DRAM exactly once.
// ---------------------------------------------------------------------------
__global__ __launch_bounds__(256) void fused_kernel(
    const float4* __restrict__ x4,
    const float*  __restrict__ w1,
    const float*  __restrict__ w2,
    float4*       __restrict__ out4)
{
    __shared__ float4 xs[CPIX * C4];   // 32 KB chunk cache
    __shared__ float4 red[4 * C4];     // 4 KB cross-subgroup reduce
    __shared__ float  s[C];
    __shared__ float  h[CR];
    __shared__ int    s_last;

    const int chunk = blockIdx.x;
    const int b     = blockIdx.y;
    const int tid   = threadIdx.x;
    const int c4    = tid & (C4 - 1);
    const int pr    = tid >> 6;        // 0..3 pixel subgroup

    const size_t base = ((size_t)(b * HW + chunk * CPIX)) * C4 + c4;

    // ---- Phase 1: load chunk into SMEM + partial sum -----------------------
    float4 acc = make_float4(0.f, 0.f, 0.f, 0.f);
#pragma unroll
    for (int i = 0; i < CPIX / 4; ++i) {        // 8 independent LDG.128
        const int p = i * 4 + pr;
        float4 v = __ldcs(&x4[base + (size_t)p * C4]);
        xs[p * C4 + c4] = v;
        acc.x += v.x; acc.y += v.y; acc.z += v.z; acc.w += v.w;
    }
    red[pr * C4 + c4] = acc;
    __syncthreads();

    if (tid < C4) {
        float4 a  = red[tid];
        float4 b1 = red[tid + 64];
        float4 c1 = red[tid + 128];
        float4 d1 = red[tid + 192];
        a.x += b1.x + c1.x + d1.x;
        a.y += b1.y + c1.y + d1.y;
        a.z += b1.z + c1.z + d1.z;
        a.w += b1.w + c1.w + d1.w;
        ((float4*)g_partial)[(b * NCHUNK + chunk) * C4 + tid] = a;
        __threadfence();               // publish partial before counter bump
    }
    __syncthreads();

    if (tid == 0) {
        int old = atomicAdd(&g_count[b], 1);
        s_last = (old == NCHUNK - 1);
    }
    __syncthreads();

    // ---- Gate computation / wait ------------------------------------------
    if (s_last) {
        // Last block of this batch: reduce partials + FC + publish gate.
        float sum = 0.0f;
#pragma unroll 7
        for (int k = 0; k < NCHUNK; ++k) {
            sum += __ldcg(&g_partial[(b * NCHUNK + k) * C + tid]);
        }
        s[tid] = sum * (1.0f / (float)HW);
        __syncthreads();

        if (tid < CR) {
            float a2 = 0.0f;
#pragma unroll 8
            for (int c = 0; c < C; ++c) {
                a2 += s[c] * w1[c * CR + tid];
            }
            h[tid] = fminf(fmaxf(a2, 0.0f), 6.0f);
        }
        __syncthreads();

        float a2 = 0.0f;
#pragma unroll
        for (int r = 0; r < CR; ++r) {
            a2 += h[r] * w2[r * C + tid];
        }
        float gate = fminf(fmaxf(a2 + 3.0f, 0.0f), 6.0f) * (1.0f / 6.0f);
        g_gate[b * C + tid] = gate;
        __threadfence();               // every writing thread fences
        __syncthreads();
        if (tid == 0) g_flag[b] = 1;   // volatile store (bypasses L1)
    } else {
        if (tid == 0) {
            while (g_flag[b] == 0) { __nanosleep(200); }
            __threadfence();
        }
        __syncthreads();
    }

    // ---- Phase 2: gated multiply from SMEM, streaming store ----------------
    const float4 gv = __ldcg(&((const float4*)g_gate)[b * C4 + c4]);

#pragma unroll
    for (int i = 0; i < CPIX / 4; ++i) {
        const int p = i * 4 + pr;
        float4 v = xs[p * C4 + c4];
        v.x *= gv.x; v.y *= gv.y; v.z *= gv.z; v.w *= gv.w;
        __stcs(&out4[base + (size_t)p * C4], v);
    }
}

extern "C" void kernel_launch(void* const* d_in, const int* in_sizes, int n_in,
                              void* d_out, int out_size) {
    const float* x  = (const float*)d_in[0];
    const float* w1 = (const float*)d_in[1];
    const float* w2 = (const float*)d_in[2];
    float* out      = (float*)d_out;

    init_kernel<<<1, 64>>>();

    dim3 grid(NCHUNK, BATCH);
    fused_kernel<<<grid, 256>>>((const float4*)x, w1, w2, (float4*)out);
}

// round 4
// speedup vs baseline: 1.4512x; 1.4512x over previous
#include <cuda_runtime.h>

#define BATCH  32
#define HW     3136
#define C      256
#define C4     64            // C/4
#define CR     64
#define CHUNKS 49
#define PPC    64            // pixels per chunk (HW / CHUNKS)
#define BPG    16            // batches per group
#define GROUPS 2

// Scratch (allocation-free per harness rules)
__device__ float g_partial[BATCH * CHUNKS * C];
__device__ float g_gate[BATCH * C];
__device__ int   g_count[BATCH];     // zero-initialized; each use resets itself

// ---------------------------------------------------------------------------
// gap_kernel: grid = (CHUNKS, BPG), block = 256.
// Streams 64 pixels x 256 ch per block (cached loads -> x stays hot in L2),
// writes the partial sum. The LAST block of each batch (atomic counter, no
// spin) additionally reduces the 49 partials and runs squeeze->relu6->excite
// ->hsigmoid, publishing the 256-float gate. It resets its counter so the
// next graph replay starts clean.
// ---------------------------------------------------------------------------
__global__ __launch_bounds__(256) void gap_kernel(
    const float4* __restrict__ x4,
    const float*  __restrict__ w1,
    const float*  __restrict__ w2,
    int b0)
{
    const int chunk = blockIdx.x;
    const int b     = b0 + blockIdx.y;
    const int tid   = threadIdx.x;
    const int c4    = tid & (C4 - 1);
    const int pr    = tid >> 6;

    const size_t base = ((size_t)(b * HW + chunk * PPC + pr)) * C4 + c4;

    float4 acc = make_float4(0.f, 0.f, 0.f, 0.f);
#pragma unroll
    for (int i = 0; i < PPC / 4; ++i) {            // 16 independent LDG.128
        float4 v = x4[base + (size_t)i * 4 * C4];  // cached: leaves x in L2
        acc.x += v.x; acc.y += v.y; acc.z += v.z; acc.w += v.w;
    }

    __shared__ float4 red[256];
    __shared__ int    s_last;
    red[tid] = acc;
    __syncthreads();

    if (tid < C4) {
        float4 a  = red[tid];
        float4 b1 = red[tid + 64];
        float4 c1 = red[tid + 128];
        float4 d1 = red[tid + 192];
        a.x += b1.x + c1.x + d1.x;
        a.y += b1.y + c1.y + d1.y;
        a.z += b1.z + c1.z + d1.z;
        a.w += b1.w + c1.w + d1.w;
        ((float4*)g_partial)[(b * CHUNKS + chunk) * C4 + tid] = a;
        __threadfence();       // publish partial before the counter bump
    }
    __syncthreads();

    if (tid == 0) {
        s_last = (atomicAdd(&g_count[b], 1) == CHUNKS - 1);
    }
    __syncthreads();
    if (!s_last) return;

    // ---- last block of batch b: reduce partials + FC + publish gate -------
    __shared__ float s[C];
    __shared__ float h[CR];

    float sum = 0.0f;
#pragma unroll 7
    for (int k = 0; k < CHUNKS; ++k) {
        sum += __ldcg(&g_partial[(b * CHUNKS + k) * C + tid]);
    }
    s[tid] = sum * (1.0f / (float)HW);
    __syncthreads();

    if (tid < CR) {
        float a2 = 0.0f;
#pragma unroll 8
        for (int c = 0; c < C; ++c) {
            a2 += s[c] * w1[c * CR + tid];
        }
        h[tid] = fminf(fmaxf(a2, 0.0f), 6.0f);
    }
    __syncthreads();

    float a2 = 0.0f;
#pragma unroll
    for (int r = 0; r < CR; ++r) {
        a2 += h[r] * w2[r * C + tid];
    }
    g_gate[b * C + tid] = fminf(fmaxf(a2 + 3.0f, 0.0f), 6.0f) * (1.0f / 6.0f);

    if (tid == 0) g_count[b] = 0;      // reset for next graph replay
}

// ---------------------------------------------------------------------------
// mul_kernel: grid = (CHUNKS, BPG), block = 256.
// Reads x (expected L2-hit: gap just streamed this group), multiplies by the
// per-(b,c) gate held in a register, streaming-stores out (evict-first so the
// write stream doesn't evict x for later blocks). Loads batched in groups of
// 8 for MLP.
// ---------------------------------------------------------------------------
__global__ __launch_bounds__(256) void mul_kernel(
    const float4* __restrict__ x4,
    float4*       __restrict__ out4,
    int b0)
{
    const int chunk = blockIdx.x;
    const int b     = b0 + blockIdx.y;
    const int tid   = threadIdx.x;
    const int c4    = tid & (C4 - 1);
    const int pr    = tid >> 6;

    const float4 gv = __ldcg(&((const float4*)g_gate)[b * C4 + c4]);
    const size_t base = ((size_t)(b * HW + chunk * PPC + pr)) * C4 + c4;

#pragma unroll
    for (int half = 0; half < 2; ++half) {
        float4 v[8];
#pragma unroll
        for (int i = 0; i < 8; ++i) {              // 8 loads in flight
            v[i] = __ldcg(&x4[base + (size_t)(half * 8 + i) * 4 * C4]);
        }
#pragma unroll
        for (int i = 0; i < 8; ++i) {
            v[i].x *= gv.x; v[i].y *= gv.y; v[i].z *= gv.z; v[i].w *= gv.w;
            __stcs(&out4[base + (size_t)(half * 8 + i) * 4 * C4], v[i]);
        }
    }
}

extern "C" void kernel_launch(void* const* d_in, const int* in_sizes, int n_in,
                              void* d_out, int out_size) {
    const float* x  = (const float*)d_in[0];
    const float* w1 = (const float*)d_in[1];
    const float* w2 = (const float*)d_in[2];
    float* out      = (float*)d_out;

    dim3 grid(CHUNKS, BPG);
    for (int g = 0; g < GROUPS; ++g) {
        const int b0 = g * BPG;
        gap_kernel<<<grid, 256>>>((const float4*)x, w1, w2, b0);
        mul_kernel<<<grid, 256>>>((const float4*)x, (float4*)out, b0);
    }
}

// round 5
// speedup vs baseline: 1.4801x; 1.0199x over previous
#include <cuda_runtime.h>

#define BATCH  32
#define HW     3136
#define C      256
#define C4     64            // C/4
#define CR     64
#define PPC    16            // pixels per chunk
#define CHUNKS 196           // HW / PPC

// Scratch (allocation-free per harness rules)
__device__ float g_partial[BATCH * CHUNKS * C];
__device__ float g_gate[BATCH * C];

// ---------------------------------------------------------------------------
// gap_kernel: grid = (CHUNKS, BATCH) = 6272 blocks, block = 256, lean (~31
// regs). Each thread: 4 independent LDG.128 (L1-bypass, L2-allocate so x is
// left hot in L2 for mul). Smem reduce across the 4 pixel subgroups.
// ---------------------------------------------------------------------------
__global__ __launch_bounds__(256) void gap_kernel(const float4* __restrict__ x4)
{
    const int chunk = blockIdx.x;
    const int b     = blockIdx.y;
    const int tid   = threadIdx.x;
    const int c4    = tid & (C4 - 1);
    const int pr    = tid >> 6;

    const size_t base = ((size_t)(b * HW + chunk * PPC + pr)) * C4 + c4;

    float4 v0 = __ldcg(&x4[base]);
    float4 v1 = __ldcg(&x4[base +  4 * C4]);
    float4 v2 = __ldcg(&x4[base +  8 * C4]);
    float4 v3 = __ldcg(&x4[base + 12 * C4]);

    float4 acc;
    acc.x = (v0.x + v1.x) + (v2.x + v3.x);
    acc.y = (v0.y + v1.y) + (v2.y + v3.y);
    acc.z = (v0.z + v1.z) + (v2.z + v3.z);
    acc.w = (v0.w + v1.w) + (v2.w + v3.w);

    __shared__ float4 red[256];
    red[tid] = acc;
    __syncthreads();

    if (tid < C4) {
        float4 a  = red[tid];
        float4 b1 = red[tid + 64];
        float4 c1 = red[tid + 128];
        float4 d1 = red[tid + 192];
        a.x += b1.x + c1.x + d1.x;
        a.y += b1.y + c1.y + d1.y;
        a.z += b1.z + c1.z + d1.z;
        a.w += b1.w + c1.w + d1.w;
        ((float4*)g_partial)[(b * CHUNKS + chunk) * C4 + tid] = a;
    }
}

// ---------------------------------------------------------------------------
// fc_kernel: 32 blocks x 256 threads. Reduce 196 partials -> mean -> w1 ->
// relu6 -> w2 -> hsigmoid -> gate.
// ---------------------------------------------------------------------------
__global__ __launch_bounds__(256) void fc_kernel(const float* __restrict__ w1,
                                                 const float* __restrict__ w2)
{
    const int b = blockIdx.x;
    const int t = threadIdx.x;

    __shared__ float s[C];
    __shared__ float h[CR];

    float sum = 0.0f;
#pragma unroll 4
    for (int k = 0; k < CHUNKS; ++k) {
        sum += __ldcg(&g_partial[(b * CHUNKS + k) * C + t]);
    }
    s[t] = sum * (1.0f / (float)HW);
    __syncthreads();

    if (t < CR) {
        float acc = 0.0f;
#pragma unroll 8
        for (int c = 0; c < C; ++c) {
            acc += s[c] * w1[c * CR + t];
        }
        h[t] = fminf(fmaxf(acc, 0.0f), 6.0f);
    }
    __syncthreads();

    float acc = 0.0f;
#pragma unroll
    for (int r = 0; r < CR; ++r) {
        acc += h[r] * w2[r * C + t];
    }
    g_gate[b * C + t] = fminf(fmaxf(acc + 3.0f, 0.0f), 6.0f) * (1.0f / 6.0f);
}

// ---------------------------------------------------------------------------
// mul_kernel: grid = (CHUNKS, BATCH) = 6272 blocks, block = 256, lean regs.
// Reads x (expected L2-hit — gap left it resident), multiplies by the per-
// (b,c4) gate held in a register, streaming-stores (evict-first) to out.
// ---------------------------------------------------------------------------
__global__ __launch_bounds__(256) void mul_kernel(const float4* __restrict__ x4,
                                                  float4* __restrict__ out4)
{
    const int chunk = blockIdx.x;
    const int b     = blockIdx.y;
    const int tid   = threadIdx.x;
    const int c4    = tid & (C4 - 1);
    const int pr    = tid >> 6;

    const float4 gv = __ldcg(&((const float4*)g_gate)[b * C4 + c4]);
    const size_t base = ((size_t)(b * HW + chunk * PPC + pr)) * C4 + c4;

    float4 v0 = __ldcg(&x4[base]);
    float4 v1 = __ldcg(&x4[base +  4 * C4]);
    float4 v2 = __ldcg(&x4[base +  8 * C4]);
    float4 v3 = __ldcg(&x4[base + 12 * C4]);

    v0.x *= gv.x; v0.y *= gv.y; v0.z *= gv.z; v0.w *= gv.w;
    v1.x *= gv.x; v1.y *= gv.y; v1.z *= gv.z; v1.w *= gv.w;
    v2.x *= gv.x; v2.y *= gv.y; v2.z *= gv.z; v2.w *= gv.w;
    v3.x *= gv.x; v3.y *= gv.y; v3.z *= gv.z; v3.w *= gv.w;

    __stcs(&out4[base],           v0);
    __stcs(&out4[base +  4 * C4], v1);
    __stcs(&out4[base +  8 * C4], v2);
    __stcs(&out4[base + 12 * C4], v3);
}

extern "C" void kernel_launch(void* const* d_in, const int* in_sizes, int n_in,
                              void* d_out, int out_size) {
    const float* x  = (const float*)d_in[0];
    const float* w1 = (const float*)d_in[1];
    const float* w2 = (const float*)d_in[2];
    float* out      = (float*)d_out;

    dim3 grid(CHUNKS, BATCH);
    gap_kernel<<<grid, 256>>>((const float4*)x);
    fc_kernel<<<BATCH, 256>>>(w1, w2);
    mul_kernel<<<grid, 256>>>((const float4*)x, (float4*)out);
}